// round 9
// baseline (speedup 1.0000x reference)
#include <cuda_runtime.h>
#include <cuda_bf16.h>
#include <mma.h>
#include <cstdint>

using namespace nvcuda;

// Problem constants (fixed by the dataset)
#define T_ 2048
#define B_ 64
#define H_ 128
#define G_ 384          // 3*H
#define C_ 32
#define M_ (T_ * B_)    // 131072 rows
#define V_ 50257

// ---------------- scratch (device globals; no allocation allowed) ----------
__device__ float g_gi0[(size_t)M_ * G_];           // layer-0 input gates [T,B,384]
__device__ float g_gi1[(size_t)M_ * G_];           // layer-1 input gates [T,B,384]
__device__ float g_y[(size_t)M_ * H_];             // layer-1 output, [B, T, 128]
__device__ __nv_bfloat16 g_hseq_hi[(size_t)M_ * H_];   // layer-0 out hi, [T,B,128]
__device__ __nv_bfloat16 g_hseq_lo[(size_t)M_ * H_];   // layer-0 out lo
__device__ __nv_bfloat16 g_emb_hi[(size_t)V_ * H_];
__device__ __nv_bfloat16 g_emb_lo[(size_t)V_ * H_];
__device__ __nv_bfloat16 g_w0_hi[G_ * H_];
__device__ __nv_bfloat16 g_w0_lo[G_ * H_];
__device__ __nv_bfloat16 g_w1_hi[G_ * H_];
__device__ __nv_bfloat16 g_w1_lo[G_ * H_];

// pipeline flags
#define NCHUNK 64                    // 64 chunks of 32 timesteps
#define NSTRIPS 1024                 // worker strips (4 m-tiles each)
#define STRIPS_PER_CHUNK 16
__device__ int g_cnt0[NCHUNK];       // L0 chunks done (counts to 64 CTAs)
__device__ int g_gcnt1[NCHUNK];      // gi1 strips done per chunk (counts to 16)
__device__ int g_ticket;             // worker strip ticket
__device__ int g_t0;                 // gemm0 strip ticket

// ---------------- helpers ---------------------------------------------------
static __device__ __forceinline__ uint32_t smem_u32(const void* p) {
    uint32_t a;
    asm("{ .reg .u64 t; cvta.to.shared.u64 t, %1; cvt.u32.u64 %0, t; }" : "=r"(a) : "l"(p));
    return a;
}
#define BAR_SYNC(id, cnt)   asm volatile("bar.sync %0, %1;"   :: "r"(id), "r"(cnt) : "memory")
#define BAR_ARRIVE(id, cnt) asm volatile("bar.arrive %0, %1;" :: "r"(id), "r"(cnt) : "memory")
#define CP_ASYNC16(dst, src) \
    asm volatile("cp.async.cg.shared.global [%0], [%1], 16;" :: "r"(dst), "l"(src) : "memory")
#define CP_COMMIT() asm volatile("cp.async.commit_group;" ::: "memory")
#define CP_WAIT(n)  asm volatile("cp.async.wait_group %0;" :: "n"(n) : "memory")

static __device__ __forceinline__ unsigned long long pk2(float a, float b) {
    unsigned long long r;
    asm("mov.b64 %0, {%1,%2};" : "=l"(r) : "f"(a), "f"(b));
    return r;
}
static __device__ __forceinline__ void upk2(unsigned long long v, float& a, float& b) {
    asm("mov.b64 {%0,%1}, %2;" : "=f"(a), "=f"(b) : "l"(v));
}
static __device__ __forceinline__ unsigned long long fma2(
    unsigned long long a, unsigned long long b, unsigned long long c) {
    unsigned long long d;
    asm("fma.rn.f32x2 %0, %1, %2, %3;" : "=l"(d) : "l"(a), "l"(b), "l"(c));
    return d;
}
static __device__ __forceinline__ float sigm(float x) {
    return __fdividef(1.0f, 1.0f + __expf(-x));
}
static __device__ __forceinline__ float tanh_fast(float x) {
    x = fminf(15.0f, fmaxf(-15.0f, x));
    float e = __expf(2.0f * x);
    return __fdividef(e - 1.0f, e + 1.0f);
}

// ---------------- fp32 -> bf16 hi/lo split conversion ----------------------
__global__ __launch_bounds__(256) void convert_kernel(
    const float* __restrict__ emb, const float* __restrict__ w0,
    const float* __restrict__ w1)
{
    long i = (long)blockIdx.x * 256 + threadIdx.x;
    const long NE = (long)V_ * H_;
    const long NW = (long)G_ * H_;
    if (i < NE) {
        float v = emb[i];
        __nv_bfloat16 h = __float2bfloat16(v);
        g_emb_hi[i] = h;
        g_emb_lo[i] = __float2bfloat16(v - __bfloat162float(h));
        return;
    }
    long j = i - NE;
    if (j < NW) {
        float v = w0[j];
        __nv_bfloat16 h = __float2bfloat16(v);
        g_w0_hi[j] = h;
        g_w0_lo[j] = __float2bfloat16(v - __bfloat162float(h));
        return;
    }
    j -= NW;
    if (j < NW) {
        float v = w1[j];
        __nv_bfloat16 h = __float2bfloat16(v);
        g_w1_hi[j] = h;
        g_w1_lo[j] = __float2bfloat16(v - __bfloat162float(h));
    }
}

// ---------------- flag reset (every replay, FIRST launch) -------------------
__global__ void zero_flags() {
    int i = threadIdx.x;
    if (i < NCHUNK) { g_cnt0[i] = 0; g_gcnt1[i] = 0; }
    if (i == 0) { g_ticket = 0; g_t0 = 0; }
}

// ---------------- shared GEMM tile machinery --------------------------------
// Tile 128(M) x 96(N), K=128, bf16 hi/lo (3 MMA terms), 12 warps of 32x32.
// smem layout (dynamic):
//   A stage0 hi @0        (34816 = 128*136*2)
//   A stage0 lo @34816
//   A stage1 hi @69632
//   A stage1 lo @104448
//   W hi       @139264    (26112 = 96*136*2)
//   W lo       @165376
#define LDM 136
#define A_HI0 0
#define A_ST  69632        // stage stride
#define A_LOD 34816        // lo offset within stage
#define W_HI  139264
#define W_LO  165376
#define SMEMSZ 191488

static __device__ __forceinline__ void compute_tile(
    const char* dsm, int stage,
    float* __restrict__ Cout, int bm, int bn)
{
    const __nv_bfloat16* Ah = (const __nv_bfloat16*)(dsm + stage * A_ST);
    const __nv_bfloat16* Al = (const __nv_bfloat16*)(dsm + stage * A_ST + A_LOD);
    const __nv_bfloat16* Wh = (const __nv_bfloat16*)(dsm + W_HI);
    const __nv_bfloat16* Wl = (const __nv_bfloat16*)(dsm + W_LO);
    const int w  = threadIdx.x >> 5;
    const int wr = w / 3;          // 0..3 -> M offset wr*32
    const int wc = w % 3;          // 0..2 -> N offset wc*32

    wmma::fragment<wmma::accumulator, 16, 16, 16, float> acc[2][2];
#pragma unroll
    for (int i = 0; i < 2; i++)
#pragma unroll
        for (int j = 0; j < 2; j++) wmma::fill_fragment(acc[i][j], 0.0f);

#pragma unroll
    for (int kc = 0; kc < 8; kc++) {
        int k0 = kc * 16;
        wmma::fragment<wmma::matrix_a, 16, 16, 16, __nv_bfloat16, wmma::row_major> fah[2], fal[2];
        wmma::fragment<wmma::matrix_b, 16, 16, 16, __nv_bfloat16, wmma::col_major> fwh[2], fwl[2];
#pragma unroll
        for (int i = 0; i < 2; i++) {
            int m0 = wr * 32 + i * 16;
            wmma::load_matrix_sync(fah[i], Ah + (size_t)m0 * LDM + k0, LDM);
            wmma::load_matrix_sync(fal[i], Al + (size_t)m0 * LDM + k0, LDM);
        }
#pragma unroll
        for (int j = 0; j < 2; j++) {
            int n0 = wc * 32 + j * 16;
            wmma::load_matrix_sync(fwh[j], Wh + (size_t)n0 * LDM + k0, LDM);
            wmma::load_matrix_sync(fwl[j], Wl + (size_t)n0 * LDM + k0, LDM);
        }
#pragma unroll
        for (int i = 0; i < 2; i++)
#pragma unroll
            for (int j = 0; j < 2; j++) {
                wmma::mma_sync(acc[i][j], fah[i], fwh[j], acc[i][j]);
                wmma::mma_sync(acc[i][j], fah[i], fwl[j], acc[i][j]);
                wmma::mma_sync(acc[i][j], fal[i], fwh[j], acc[i][j]);
            }
    }

#pragma unroll
    for (int i = 0; i < 2; i++) {
        int m = bm + wr * 32 + i * 16;
#pragma unroll
        for (int j = 0; j < 2; j++) {
            int n = bn + wc * 32 + j * 16;
            wmma::store_matrix_sync(Cout + (size_t)m * G_ + n, acc[i][j], G_,
                                    wmma::mem_row_major);
        }
    }
}

static __device__ __forceinline__ void issue_w(
    uint32_t sb, const __nv_bfloat16* w_hi, const __nv_bfloat16* w_lo, int bn)
{
    for (int idx = threadIdx.x; idx < 96 * 16; idx += 384) {
        int row = idx >> 4, ch = idx & 15;
        uint32_t d = sb + W_HI + row * (LDM * 2) + ch * 16;
        CP_ASYNC16(d, (const char*)(w_hi + (size_t)(bn + row) * H_) + ch * 16);
        CP_ASYNC16(d + (W_LO - W_HI), (const char*)(w_lo + (size_t)(bn + row) * H_) + ch * 16);
    }
}

static __device__ __forceinline__ void issue_a(
    uint32_t sb, int stage,
    const __nv_bfloat16* a_hi, const __nv_bfloat16* a_lo, int brow)
{
    uint32_t base = sb + stage * A_ST;
    for (int idx = threadIdx.x; idx < 128 * 16; idx += 384) {
        int row = idx >> 4, ch = idx & 15;
        uint32_t d = base + row * (LDM * 2) + ch * 16;
        CP_ASYNC16(d, (const char*)(a_hi + (size_t)(brow + row) * H_) + ch * 16);
        CP_ASYNC16(d + A_LOD, (const char*)(a_lo + (size_t)(brow + row) * H_) + ch * 16);
    }
}

static __device__ __forceinline__ void issue_a_gather(
    uint32_t sb, int stage, const int* __restrict__ x,
    const __nv_bfloat16* a_hi, const __nv_bfloat16* a_lo, int brow)
{
    uint32_t base = sb + stage * A_ST;
    for (int idx = threadIdx.x; idx < 128 * 16; idx += 384) {
        int row = idx >> 4, ch = idx & 15;
        int m = brow + row;
        int token = __ldg(&x[(m & (B_ - 1)) * T_ + (m >> 6)]);
        uint32_t d = base + row * (LDM * 2) + ch * 16;
        CP_ASYNC16(d, (const char*)(a_hi + (size_t)token * H_) + ch * 16);
        CP_ASYNC16(d + A_LOD, (const char*)(a_lo + (size_t)token * H_) + ch * 16);
    }
}

// ---------------- persistent gi0 GEMM (gather, cp.async double-buffered) ---
// strips: s in [0,1024): nt = s>>8, mg = s&255 -> 4 m-tiles mg*4..mg*4+3
__global__ __launch_bounds__(384, 1) void gemm0_kernel(
    const int*           __restrict__ x,
    const __nv_bfloat16* __restrict__ a_hi,
    const __nv_bfloat16* __restrict__ a_lo,
    const __nv_bfloat16* __restrict__ w_hi,
    const __nv_bfloat16* __restrict__ w_lo,
    float*               __restrict__ Cout)
{
    extern __shared__ __align__(16) char dsm[];
    __shared__ int sh_s;
    const uint32_t sb = smem_u32(dsm);
    const int tid = threadIdx.x;
    int lastnt = -1;

    for (;;) {
        if (tid == 0) sh_s = atomicAdd(&g_t0, 1);
        __syncthreads();
        int s = sh_s;
        if (s >= NSTRIPS) break;
        int nt = s >> 8, mg = s & 255;
        int bn = nt * 96;
        int mt0 = mg * 4;

        if (nt != lastnt) { lastnt = nt; issue_w(sb, w_hi, w_lo, bn); }
        issue_a_gather(sb, 0, x, a_hi, a_lo, mt0 * 128);
        CP_COMMIT();
#pragma unroll
        for (int i = 0; i < 4; i++) {
            if (i < 3) {
                issue_a_gather(sb, (i + 1) & 1, x, a_hi, a_lo, (mt0 + i + 1) * 128);
                CP_COMMIT();
                CP_WAIT(1);
            } else {
                CP_WAIT(0);
            }
            __syncthreads();
            compute_tile(dsm, i & 1, Cout, (mt0 + i) * 128, bn);
            __syncthreads();
        }
    }
}

// ---------------- fused pipeline: L0 scan | gi1 workers | L1 scan ----------

// ---- L0 scan body (split named barriers; publishes chunk flags) ----
static __device__ __forceinline__ void scan_l0(
    char* dsm, int b,
    const float* __restrict__ gi,
    const float* __restrict__ whh,
    const float* __restrict__ bih,
    const float* __restrict__ bhh,
    __nv_bfloat16* __restrict__ out_hi,
    __nv_bfloat16* __restrict__ out_lo)
{
    float* h_sh = (float*)dsm;          // [128], 16B aligned
    float* r_sh = h_sh + H_;
    float* z_sh = r_sh + H_;

    const int g   = threadIdx.x;
    const int grp = g >> 7;
    const int j   = g & 127;

    unsigned long long w2[64];
    {
        const float4* wrow = (const float4*)(whh + (size_t)g * H_);
#pragma unroll
        for (int i = 0; i < 32; i++) {
            float4 v = wrow[i];
            w2[2 * i + 0] = pk2(v.x, v.y);
            w2[2 * i + 1] = pk2(v.z, v.w);
        }
    }
    const float bh = bhh[g];
    const float bi = bih[g];

    if (g < H_) h_sh[g] = 0.0f;
    float gic = gi[(size_t)b * G_ + g] + bi;
    __syncthreads();

    const unsigned long long z64 = pk2(0.0f, 0.0f);

    for (int t = 0; t < T_; t++) {
        float ginext = 0.0f;
        if (t + 1 < T_)
            ginext = gi[((size_t)(t + 1) * B_ + b) * G_ + g] + bi;

        unsigned long long acc0 = pk2(bh, 0.0f);
        unsigned long long acc1 = z64, acc2 = z64, acc3 = z64;
        const ulonglong2* hq = (const ulonglong2*)h_sh;
#pragma unroll
        for (int i = 0; i < 16; i++) {
            ulonglong2 hv0 = hq[2 * i + 0];
            ulonglong2 hv1 = hq[2 * i + 1];
            acc0 = fma2(w2[4 * i + 0], hv0.x, acc0);
            acc1 = fma2(w2[4 * i + 1], hv0.y, acc1);
            acc2 = fma2(w2[4 * i + 2], hv1.x, acc2);
            acc3 = fma2(w2[4 * i + 3], hv1.y, acc3);
        }
        float a0, a1, a2, a3, a4, a5, a6, a7;
        upk2(acc0, a0, a1); upk2(acc1, a2, a3);
        upk2(acc2, a4, a5); upk2(acc3, a6, a7);
        float ghval = ((a0 + a2) + (a1 + a3)) + ((a4 + a6) + (a5 + a7));

        if (grp == 0) {
            r_sh[j] = sigm(gic + ghval);
            BAR_ARRIVE(1, 384);
            BAR_SYNC(2, 384);                 // wait for h update
        } else if (grp == 1) {
            z_sh[j] = sigm(gic + ghval);
            BAR_ARRIVE(1, 384);
            BAR_SYNC(2, 384);
        } else {
            BAR_SYNC(1, 384);                 // wait for r/z
            float n  = tanh_fast(gic + r_sh[j] * ghval);
            float z  = z_sh[j];
            float hn = (1.0f - z) * n + z * h_sh[j];
            h_sh[j] = hn;
            size_t o = ((size_t)t * B_ + b) * H_ + j;
            __nv_bfloat16 hh = __float2bfloat16(hn);
            out_hi[o] = hh;
            out_lo[o] = __float2bfloat16(hn - __bfloat162float(hh));
            bool bd = (t & 31) == 31;
            if (bd) __threadfence();          // release this chunk's gmem stores
            BAR_ARRIVE(2, 384);
            BAR_SYNC(3, 128);                 // intra-grp2: all h writes visible
            if (bd && j == 0) atomicAdd(&g_cnt0[t >> 5], 1);
        }
        gic = ginext;
    }
}

// ---- L1 scan body (split barriers; waits on gi1 strip flags) ----
static __device__ __forceinline__ void scan_l1(
    char* dsm, int b,
    const float* __restrict__ gi,
    const float* __restrict__ whh,
    const float* __restrict__ bih,
    const float* __restrict__ bhh,
    float* __restrict__ out_f32)
{
    float* h_sh = (float*)dsm;
    float* r_sh = h_sh + H_;
    float* z_sh = r_sh + H_;

    const int g   = threadIdx.x;
    const int grp = g >> 7;
    const int j   = g & 127;

    unsigned long long w2[64];
    {
        const float4* wrow = (const float4*)(whh + (size_t)g * H_);
#pragma unroll
        for (int i = 0; i < 32; i++) {
            float4 v = wrow[i];
            w2[2 * i + 0] = pk2(v.x, v.y);
            w2[2 * i + 1] = pk2(v.z, v.w);
        }
    }
    const float bh = bhh[g];
    const float bi = bih[g];

    if (g < H_) h_sh[g] = 0.0f;
    __syncthreads();

    if (g == 0)
        while (*(volatile int*)&g_gcnt1[0] < STRIPS_PER_CHUNK) __nanosleep(128);
    __syncthreads();
    float gic = __ldcg(&gi[(size_t)b * G_ + g]) + bi;

    const unsigned long long z64 = pk2(0.0f, 0.0f);

    for (int t = 0; t < T_; t++) {
        bool newchunk = ((t + 1) < T_) && (((t + 1) & 31) == 0);
        float ginext = 0.0f;
        if ((t + 1 < T_) && !newchunk)
            ginext = __ldcg(&gi[((size_t)(t + 1) * B_ + b) * G_ + g]) + bi;

        unsigned long long acc0 = pk2(bh, 0.0f);
        unsigned long long acc1 = z64, acc2 = z64, acc3 = z64;
        const ulonglong2* hq = (const ulonglong2*)h_sh;
#pragma unroll
        for (int i = 0; i < 16; i++) {
            ulonglong2 hv0 = hq[2 * i + 0];
            ulonglong2 hv1 = hq[2 * i + 1];
            acc0 = fma2(w2[4 * i + 0], hv0.x, acc0);
            acc1 = fma2(w2[4 * i + 1], hv0.y, acc1);
            acc2 = fma2(w2[4 * i + 2], hv1.x, acc2);
            acc3 = fma2(w2[4 * i + 3], hv1.y, acc3);
        }
        float a0, a1, a2, a3, a4, a5, a6, a7;
        upk2(acc0, a0, a1); upk2(acc1, a2, a3);
        upk2(acc2, a4, a5); upk2(acc3, a6, a7);
        float ghval = ((a0 + a2) + (a1 + a3)) + ((a4 + a6) + (a5 + a7));

        if (grp == 0) {
            r_sh[j] = sigm(gic + ghval);
            BAR_ARRIVE(1, 384);
            BAR_SYNC(2, 384);
        } else if (grp == 1) {
            z_sh[j] = sigm(gic + ghval);
            BAR_ARRIVE(1, 384);
            BAR_SYNC(2, 384);
        } else {
            BAR_SYNC(1, 384);
            float n  = tanh_fast(gic + r_sh[j] * ghval);
            float z  = z_sh[j];
            float hn = (1.0f - z) * n + z * h_sh[j];
            h_sh[j] = hn;
            out_f32[((size_t)b * T_ + t) * H_ + j] = hn;
            BAR_ARRIVE(2, 384);
            BAR_SYNC(3, 128);
        }

        if (newchunk) {
            BAR_SYNC(0, 384);                 // full CTA alignment
            if (g == 0)
                while (*(volatile int*)&g_gcnt1[(t + 1) >> 5] < STRIPS_PER_CHUNK)
                    __nanosleep(128);
            BAR_SYNC(0, 384);
            gic = __ldcg(&gi[((size_t)(t + 1) * B_ + b) * G_ + g]) + bi;
        } else {
            gic = ginext;
        }
    }
}

// ---- gi1 worker: strips of 4 m-tiles, cp.async double-buffered ----
// strip s: c = s>>4, w = s&15, nt = w>>2, mg = w&3 -> m-tiles c*16+mg*4+i
static __device__ __forceinline__ void worker_gemm(
    char* dsm,
    const __nv_bfloat16* __restrict__ a_hi,
    const __nv_bfloat16* __restrict__ a_lo,
    const __nv_bfloat16* __restrict__ w_hi,
    const __nv_bfloat16* __restrict__ w_lo,
    float* __restrict__ Cout)
{
    __shared__ int sh_s;
    const uint32_t sb = smem_u32(dsm);
    const int tid = threadIdx.x;
    int lastnt = -1;

    for (;;) {
        if (tid == 0) sh_s = atomicAdd(&g_ticket, 1);
        __syncthreads();
        int s = sh_s;
        if (s >= NSTRIPS) break;
        int c  = s >> 4;
        int wb = s & 15;
        int nt = wb >> 2;
        int mg = wb & 3;
        int bn = nt * 96;
        int mt0 = c * 16 + mg * 4;

        if (tid == 0)
            while (*(volatile int*)&g_cnt0[c] < B_) __nanosleep(128);
        __syncthreads();

        if (nt != lastnt) { lastnt = nt; issue_w(sb, w_hi, w_lo, bn); }
        issue_a(sb, 0, a_hi, a_lo, mt0 * 128);
        CP_COMMIT();
#pragma unroll
        for (int i = 0; i < 4; i++) {
            if (i < 3) {
                issue_a(sb, (i + 1) & 1, a_hi, a_lo, (mt0 + i + 1) * 128);
                CP_COMMIT();
                CP_WAIT(1);
            } else {
                CP_WAIT(0);
            }
            __syncthreads();
            compute_tile(dsm, i & 1, Cout, (mt0 + i) * 128, bn);
            __syncthreads();
        }
        __threadfence();      // release gi1 stores of this strip
        __syncthreads();
        if (tid == 0) atomicAdd(&g_gcnt1[c], 1);
    }
}

__global__ __launch_bounds__(384, 1) void fused_kernel(
    const float* __restrict__ gi0,
    const float* __restrict__ whh0, const float* __restrict__ bih0,
    const float* __restrict__ bhh0,
    const float* __restrict__ whh1, const float* __restrict__ bih1,
    const float* __restrict__ bhh1,
    float* __restrict__ gi1,
    __nv_bfloat16* __restrict__ hhi, __nv_bfloat16* __restrict__ hlo,
    const __nv_bfloat16* __restrict__ w1h, const __nv_bfloat16* __restrict__ w1l,
    float* __restrict__ y)
{
    extern __shared__ __align__(16) char dsm[];
    const int bid = blockIdx.x;
    if (bid < 64) {
        scan_l0(dsm, bid, gi0, whh0, bih0, bhh0, hhi, hlo);
    } else if (bid < 128) {
        scan_l1(dsm, bid - 64, gi1, whh1, bih1, bhh1, y);
    } else {
        worker_gemm(dsm, hhi, hlo, w1h, w1l, gi1);
    }
}

// ---------------- FC: out[M,32] = relu(Y[M,128] @ fcw[32,128]^T + fcb) -----
__global__ __launch_bounds__(256) void fc_kernel(
    const float* __restrict__ Y,
    const float* __restrict__ fcw,
    const float* __restrict__ fcb,
    float*       __restrict__ out)
{
    __shared__ float Wt[128][33];
    __shared__ float As[128][33];

    const int bm  = blockIdx.x * 32;
    const int tid = threadIdx.x;

#pragma unroll
    for (int j = 0; j < 4; j++) {
        int f  = tid + j * 256;
        int c  = f >> 5;
        int kq = f & 31;
        float4 v = *(const float4*)(fcw + (size_t)c * 128 + kq * 4);
        Wt[kq * 4 + 0][c] = v.x;
        Wt[kq * 4 + 1][c] = v.y;
        Wt[kq * 4 + 2][c] = v.z;
        Wt[kq * 4 + 3][c] = v.w;
    }
#pragma unroll
    for (int j = 0; j < 4; j++) {
        int f  = tid + j * 256;
        int r  = f >> 5;
        int kq = f & 31;
        float4 v = *(const float4*)(Y + (size_t)(bm + r) * 128 + kq * 4);
        As[kq * 4 + 0][r] = v.x;
        As[kq * 4 + 1][r] = v.y;
        As[kq * 4 + 2][r] = v.z;
        As[kq * 4 + 3][r] = v.w;
    }
    __syncthreads();

    const int c  = tid & 31;
    const int rg = tid >> 5;
    float acc[4] = {0.f, 0.f, 0.f, 0.f};
#pragma unroll
    for (int k = 0; k < 128; k++) {
        float w = Wt[k][c];
#pragma unroll
        for (int i = 0; i < 4; i++) acc[i] += As[k][rg * 4 + i] * w;
    }
    float bb = fcb[c];
#pragma unroll
    for (int i = 0; i < 4; i++) {
        float v = acc[i] + bb;
        out[(size_t)(bm + rg * 4 + i) * C_ + c] = fmaxf(v, 0.0f);
    }
}

// ---------------- launch ----------------------------------------------------
extern "C" void kernel_launch(void* const* d_in, const int* in_sizes, int n_in,
                              void* d_out, int out_size)
{
    const int*   x    = (const int*)  d_in[0];
    const float* emb  = (const float*)d_in[1];
    const float* wih0 = (const float*)d_in[2];
    const float* whh0 = (const float*)d_in[3];
    const float* bih0 = (const float*)d_in[4];
    const float* bhh0 = (const float*)d_in[5];
    const float* wih1 = (const float*)d_in[6];
    const float* whh1 = (const float*)d_in[7];
    const float* bih1 = (const float*)d_in[8];
    const float* bhh1 = (const float*)d_in[9];
    const float* fcw  = (const float*)d_in[10];
    const float* fcb  = (const float*)d_in[11];
    float* out = (float*)d_out;

    void* p;
    cudaGetSymbolAddress(&p, g_gi0);     float* gi0  = (float*)p;
    cudaGetSymbolAddress(&p, g_gi1);     float* gi1  = (float*)p;
    cudaGetSymbolAddress(&p, g_y);       float* y    = (float*)p;
    cudaGetSymbolAddress(&p, g_hseq_hi); __nv_bfloat16* hhi = (__nv_bfloat16*)p;
    cudaGetSymbolAddress(&p, g_hseq_lo); __nv_bfloat16* hlo = (__nv_bfloat16*)p;
    cudaGetSymbolAddress(&p, g_emb_hi);  __nv_bfloat16* ehi = (__nv_bfloat16*)p;
    cudaGetSymbolAddress(&p, g_emb_lo);  __nv_bfloat16* elo = (__nv_bfloat16*)p;
    cudaGetSymbolAddress(&p, g_w0_hi);   __nv_bfloat16* w0h = (__nv_bfloat16*)p;
    cudaGetSymbolAddress(&p, g_w0_lo);   __nv_bfloat16* w0l = (__nv_bfloat16*)p;
    cudaGetSymbolAddress(&p, g_w1_hi);   __nv_bfloat16* w1h = (__nv_bfloat16*)p;
    cudaGetSymbolAddress(&p, g_w1_lo);   __nv_bfloat16* w1l = (__nv_bfloat16*)p;

    cudaFuncSetAttribute(gemm0_kernel, cudaFuncAttributeMaxDynamicSharedMemorySize, SMEMSZ);
    cudaFuncSetAttribute(fused_kernel, cudaFuncAttributeMaxDynamicSharedMemorySize, SMEMSZ);

    // 0) reset tickets + pipeline flags (each replay)
    zero_flags<<<1, 64>>>();

    // 1) split emb + input-gate weights into bf16 hi/lo
    long nconv = (long)V_ * H_ + 2L * G_ * H_;
    convert_kernel<<<(unsigned)((nconv + 255) / 256), 256>>>(emb, wih0, wih1);

    // 2) gi0 = gather(emb, x) @ w_ih0^T  (persistent, cp.async double-buffered)
    gemm0_kernel<<<148, 384, SMEMSZ>>>(x, ehi, elo, w0h, w0l, gi0);

    // 3) fused: L0 scan (64) | gi1 GEMM workers (20) | L1 scan (64)
    fused_kernel<<<148, 384, SMEMSZ>>>(gi0, whh0, bih0, bhh0,
                                       whh1, bih1, bhh1,
                                       gi1, hhi, hlo, w1h, w1l, y);

    // 4) out = relu(y @ fc_w^T + fc_b)
    fc_kernel<<<M_ / 32, 256>>>(y, fcw, fcb, out);
}